// round 8
// baseline (speedup 1.0000x reference)
#include <cuda_runtime.h>

// Problem constants
#define VV   32000
#define EE   256
#define HLL  1024
#define HCC  256
#define BB   512
#define TST  100

// ---------------- scratch (__device__ globals, no allocation) ----------------
__device__ float g_h[BB * HLL];
__device__ float g_gi[BB * 3 * HLL];
__device__ float g_gh[BB * 3 * HLL];
__device__ float g_gictx[BB * 3 * HLL];
__device__ float g_dec[BB * EE];
__device__ float g_logits[(size_t)BB * VV];
__device__ int   g_tok[BB];

// ---------------- threefry2x32 (Threefry-2x32, 20 rounds) ----------------
__host__ __device__ __forceinline__ unsigned int rotl32(unsigned int x, int r) {
    return (x << r) | (x >> (32 - r));
}

__host__ __device__ __forceinline__ void threefry2x32(
    unsigned int k0, unsigned int k1, unsigned int& x0, unsigned int& x1)
{
    unsigned int ks2 = k0 ^ k1 ^ 0x1BD11BDAu;
    x0 += k0; x1 += k1;
#define TF_R(r) { x0 += x1; x1 = rotl32(x1, (r)); x1 ^= x0; }
    TF_R(13) TF_R(15) TF_R(26) TF_R(6)   x0 += k1;  x1 += ks2 + 1u;
    TF_R(17) TF_R(29) TF_R(16) TF_R(24)  x0 += ks2; x1 += k0  + 2u;
    TF_R(13) TF_R(15) TF_R(26) TF_R(6)   x0 += k0;  x1 += k1  + 3u;
    TF_R(17) TF_R(29) TF_R(16) TF_R(24)  x0 += k1;  x1 += ks2 + 4u;
    TF_R(13) TF_R(15) TF_R(26) TF_R(6)   x0 += ks2; x1 += k0  + 5u;
#undef TF_R
}

// ---------------- flag-proof transcendentals (fmaf-only, faithful) ----------
// Accurate logf (njuffa faithful-rounding construction, pure fmaf).
__device__ __forceinline__ float acc_logf(float a) {
    int e = (__float_as_int(a) - 0x3f2aaaab) & 0xff800000;
    float m = __int_as_float(__float_as_int(a) - e);
    float i = (float)e * 1.19209290e-7f;   // e * 2^-23
    float f = m - 1.0f;
    float s = f * f;
    float r = fmaf(0.230836749f, f, -0.279208571f);
    float t = fmaf(0.331826031f, f, -0.498910338f);
    r = fmaf(r, s, t);
    r = fmaf(r, s, f);
    r = fmaf(i, 0.693147182f, r);
    return r;
}

// Accurate expf for moderate |a| (no overflow handling needed: |a| < 60 here).
__device__ __forceinline__ float acc_expf(float a) {
    float j = fmaf(1.442695041f, a, 12582912.0f) - 12582912.0f;  // rint(a/ln2)
    float f = fmaf(j, -6.93145752e-1f, a);   // ln2_hi
    f = fmaf(j, -1.42860677e-6f, f);         // ln2_lo
    float r = 1.37805939e-3f;
    r = fmaf(r, f, 8.37312452e-3f);
    r = fmaf(r, f, 4.16695364e-2f);
    r = fmaf(r, f, 1.66664720e-1f);
    r = fmaf(r, f, 4.99999851e-1f);
    r = fmaf(r, f, 1.0f);
    r = fmaf(r, f, 1.0f);
    int i = (int)j;
    return r * __int_as_float((127 + i) << 23);
}

__device__ __forceinline__ float acc_sigmoid(float x) {
    return 1.0f / (1.0f + acc_expf(-x));
}

__device__ __forceinline__ float acc_tanh(float x) {
    float t = acc_expf(2.0f * x);
    return (t - 1.0f) / (t + 1.0f);
}

__device__ __forceinline__ float gumbel_from_bits(unsigned int bits) {
    // jax.random.uniform(minval=tiny, maxval=1) then -log(-log(u))
    float f = __uint_as_float((bits >> 9) | 0x3f800000u) - 1.0f;
    const float TINY = 1.17549435e-38f;
    float u = fmaxf(TINY, f + TINY);
    return -acc_logf(-acc_logf(u));
}

// ---------------- init ----------------
__global__ void init_kernel(const float* __restrict__ lang_h0,
                            const int* __restrict__ inpt0,
                            float* __restrict__ out)
{
    int idx = blockIdx.x * blockDim.x + threadIdx.x;
    if (idx < BB * HLL) {
        float v = lang_h0[idx];
        g_h[idx] = v;
        out[(size_t)TST * BB + idx] = v;   // all_lang_hs slot 0
    }
    if (idx < BB) g_tok[idx] = inpt0[idx];
}

// ---------------- SGEMM 64x64x16, C = A(or gathered-A) * B^T (+bias +addM) ---
__global__ void __launch_bounds__(256) sgemm64(
    const float* __restrict__ A, int lda, const int* __restrict__ arow,
    const float* __restrict__ Bm, int ldb,
    float* __restrict__ C, int ldc, int K,
    const float* __restrict__ bias,
    const float* __restrict__ addM, int ldadd)
{
    __shared__ float As[16 * 68];
    __shared__ float Bs[16 * 68];
    int tid = threadIdx.x;
    int tx = tid & 15, ty = tid >> 4;
    int m0 = blockIdx.y * 64, n0 = blockIdx.x * 64;
    int lr = tid >> 2;          // 0..63
    int lk = (tid & 3) * 4;     // 0,4,8,12

    int am = arow ? arow[m0 + lr] : (m0 + lr);
    const float* aptr = A + (size_t)am * lda + lk;
    const float* bptr = Bm + (size_t)(n0 + lr) * ldb + lk;

    float acc[4][4] = {};
    int nkt = K / 16;
    float4 ra = *(const float4*)aptr;
    float4 rb = *(const float4*)bptr;

    for (int kt = 0; kt < nkt; ++kt) {
        As[(lk + 0) * 68 + lr] = ra.x; As[(lk + 1) * 68 + lr] = ra.y;
        As[(lk + 2) * 68 + lr] = ra.z; As[(lk + 3) * 68 + lr] = ra.w;
        Bs[(lk + 0) * 68 + lr] = rb.x; Bs[(lk + 1) * 68 + lr] = rb.y;
        Bs[(lk + 2) * 68 + lr] = rb.z; Bs[(lk + 3) * 68 + lr] = rb.w;
        __syncthreads();
        if (kt + 1 < nkt) {
            ra = *(const float4*)(aptr + (kt + 1) * 16);
            rb = *(const float4*)(bptr + (kt + 1) * 16);
        }
#pragma unroll
        for (int k = 0; k < 16; ++k) {
            float4 a = *(const float4*)&As[k * 68 + ty * 4];
            float4 b = *(const float4*)&Bs[k * 68 + tx * 4];
            float av[4] = {a.x, a.y, a.z, a.w};
            float bv[4] = {b.x, b.y, b.z, b.w};
#pragma unroll
            for (int i = 0; i < 4; ++i)
#pragma unroll
                for (int j = 0; j < 4; ++j)
                    acc[i][j] += av[i] * bv[j];
        }
        __syncthreads();
    }

#pragma unroll
    for (int i = 0; i < 4; ++i) {
        int m = m0 + ty * 4 + i;
#pragma unroll
        for (int j = 0; j < 4; ++j) {
            int n = n0 + tx * 4 + j;
            float v = acc[i][j];
            if (bias) v += bias[n];
            if (addM) v += addM[(size_t)m * ldadd + n];
            C[(size_t)m * ldc + n] = v;
        }
    }
}

// ---------------- SGEMM 128x128x16 (logits), C = A * B^T ---------------------
__global__ void __launch_bounds__(256) sgemm128(
    const float* __restrict__ A, int lda,
    const float* __restrict__ Bm, int ldb,
    float* __restrict__ C, int ldc, int K)
{
    __shared__ float As[16 * 132];
    __shared__ float Bs[16 * 132];
    int tid = threadIdx.x;
    int tx = tid & 15, ty = tid >> 4;
    int m0 = blockIdx.y * 128, n0 = blockIdx.x * 128;
    int lr = tid >> 2;
    int lk = (tid & 3) * 4;

    const float* aptr0 = A + (size_t)(m0 + lr) * lda + lk;
    const float* aptr1 = A + (size_t)(m0 + lr + 64) * lda + lk;
    const float* bptr0 = Bm + (size_t)(n0 + lr) * ldb + lk;
    const float* bptr1 = Bm + (size_t)(n0 + lr + 64) * ldb + lk;

    float acc[8][8] = {};
    int nkt = K / 16;
    float4 ra0 = *(const float4*)aptr0;
    float4 ra1 = *(const float4*)aptr1;
    float4 rb0 = *(const float4*)bptr0;
    float4 rb1 = *(const float4*)bptr1;

    for (int kt = 0; kt < nkt; ++kt) {
        As[(lk + 0) * 132 + lr] = ra0.x; As[(lk + 1) * 132 + lr] = ra0.y;
        As[(lk + 2) * 132 + lr] = ra0.z; As[(lk + 3) * 132 + lr] = ra0.w;
        As[(lk + 0) * 132 + lr + 64] = ra1.x; As[(lk + 1) * 132 + lr + 64] = ra1.y;
        As[(lk + 2) * 132 + lr + 64] = ra1.z; As[(lk + 3) * 132 + lr + 64] = ra1.w;
        Bs[(lk + 0) * 132 + lr] = rb0.x; Bs[(lk + 1) * 132 + lr] = rb0.y;
        Bs[(lk + 2) * 132 + lr] = rb0.z; Bs[(lk + 3) * 132 + lr] = rb0.w;
        Bs[(lk + 0) * 132 + lr + 64] = rb1.x; Bs[(lk + 1) * 132 + lr + 64] = rb1.y;
        Bs[(lk + 2) * 132 + lr + 64] = rb1.z; Bs[(lk + 3) * 132 + lr + 64] = rb1.w;
        __syncthreads();
        if (kt + 1 < nkt) {
            ra0 = *(const float4*)(aptr0 + (kt + 1) * 16);
            ra1 = *(const float4*)(aptr1 + (kt + 1) * 16);
            rb0 = *(const float4*)(bptr0 + (kt + 1) * 16);
            rb1 = *(const float4*)(bptr1 + (kt + 1) * 16);
        }
#pragma unroll
        for (int k = 0; k < 16; ++k) {
            float4 a0 = *(const float4*)&As[k * 132 + ty * 4];
            float4 a1 = *(const float4*)&As[k * 132 + 64 + ty * 4];
            float4 b0 = *(const float4*)&Bs[k * 132 + tx * 4];
            float4 b1 = *(const float4*)&Bs[k * 132 + 64 + tx * 4];
            float av[8] = {a0.x, a0.y, a0.z, a0.w, a1.x, a1.y, a1.z, a1.w};
            float bv[8] = {b0.x, b0.y, b0.z, b0.w, b1.x, b1.y, b1.z, b1.w};
#pragma unroll
            for (int i = 0; i < 8; ++i)
#pragma unroll
                for (int j = 0; j < 8; ++j)
                    acc[i][j] += av[i] * bv[j];
        }
        __syncthreads();
    }

#pragma unroll
    for (int i = 0; i < 8; ++i) {
        int m = m0 + (i < 4 ? ty * 4 + i : 64 + ty * 4 + (i - 4));
#pragma unroll
        for (int j = 0; j < 8; ++j) {
            int n = n0 + (j < 4 ? tx * 4 + j : 64 + tx * 4 + (j - 4));
            C[(size_t)m * ldc + n] = acc[i][j];
        }
    }
}

// ---------------- GRU elementwise ----------------
__global__ void gru_act(const float* __restrict__ gi, const float* __restrict__ gh,
                        float* __restrict__ h, float* __restrict__ hs_out)
{
    int idx = blockIdx.x * blockDim.x + threadIdx.x;   // BB*HLL
    int b = idx >> 10, j = idx & 1023;
    size_t base = (size_t)b * 3072 + j;
    float ir = gi[base], iz = gi[base + 1024], in_ = gi[base + 2048];
    float hr = gh[base], hz = gh[base + 1024], hn = gh[base + 2048];
    float r = acc_sigmoid(ir + hr);
    float z = acc_sigmoid(iz + hz);
    float n = acc_tanh(in_ + r * hn);
    float hprev = h[idx];
    float hnew = (1.0f - z) * n + z * hprev;
    h[idx] = hnew;
    hs_out[idx] = hnew;
}

// ---------------- sampler: partitionable threefry + gumbel + argmax ---------
// Partitionable random_bits for 32-bit: element j (row-major flat index) uses
// cipher(key, x0 = hi32(j) = 0, x1 = lo32(j) = j); bits = out_x0 ^ out_x1.
__global__ void __launch_bounds__(256) sample_kernel(
    const float* __restrict__ logits,
    unsigned int k0, unsigned int k1,
    int* __restrict__ tok, float* __restrict__ outtok)
{
    int b = blockIdx.x;            // 0..511
    int tid = threadIdx.x;
    const float* l = logits + (size_t)b * VV;

    float best = -1e30f;
    int bi = 0;
    unsigned int jbase = (unsigned int)b * (unsigned int)VV;

    for (int v = tid; v < VV; v += 256) {
        unsigned int x0 = 0u;
        unsigned int x1 = jbase + (unsigned int)v;
        threefry2x32(k0, k1, x0, x1);
        unsigned int bits = x0 ^ x1;
        float c = l[v] + gumbel_from_bits(bits);
        if (c > best) { best = c; bi = v; }   // v strictly increasing per thread
    }

    __shared__ float sv[256];
    __shared__ int   si[256];
    sv[tid] = best; si[tid] = bi;
    __syncthreads();
    for (int s = 128; s > 0; s >>= 1) {
        if (tid < s) {
            float v2 = sv[tid + s]; int i2 = si[tid + s];
            float v1 = sv[tid];     int i1 = si[tid];
            if (v2 > v1 || (v2 == v1 && i2 < i1)) { sv[tid] = v2; si[tid] = i2; }
        }
        __syncthreads();
    }
    if (tid == 0) {
        tok[b] = si[0];
        outtok[b] = (float)si[0];
    }
}

// ---------------- host driver ----------------
extern "C" void kernel_launch(void* const* d_in, const int* in_sizes, int n_in,
                              void* d_out, int out_size)
{
    const float* lang_h0  = (const float*)d_in[0];
    const float* ctx_h    = (const float*)d_in[1];
    const float* word_emb = (const float*)d_in[2];
    const float* dec_W    = (const float*)d_in[3];
    const float* dec_b    = (const float*)d_in[4];
    const float* w_ih     = (const float*)d_in[5];
    const float* w_hh     = (const float*)d_in[6];
    const float* b_ih     = (const float*)d_in[7];
    const float* b_hh     = (const float*)d_in[8];
    const int*   inpt0    = (const int*)d_in[9];
    float* out = (float*)d_out;

    float *ph, *pgi, *pgh, *pgictx, *pdec, *plog;
    int* ptok;
    cudaGetSymbolAddress((void**)&ph, g_h);
    cudaGetSymbolAddress((void**)&pgi, g_gi);
    cudaGetSymbolAddress((void**)&pgh, g_gh);
    cudaGetSymbolAddress((void**)&pgictx, g_gictx);
    cudaGetSymbolAddress((void**)&pdec, g_dec);
    cudaGetSymbolAddress((void**)&plog, g_logits);
    cudaGetSymbolAddress((void**)&ptok, g_tok);

    // Host-side key schedule, PARTITIONABLE mode:
    // jax.random.split(key(1), 100): key_t = both outputs of
    // threefry2x32(key=(0,1), x0 = hi32(t) = 0, x1 = lo32(t) = t).
    unsigned int kk0[TST], kk1[TST];
    for (int t = 0; t < TST; ++t) {
        unsigned int x0 = 0u, x1 = (unsigned int)t;
        threefry2x32(0u, 1u, x0, x1);
        kk0[t] = x0;
        kk1[t] = x1;
    }

    init_kernel<<<2048, 256>>>(lang_h0, inpt0, out);

    // gi_ctx = ctx_h @ w_ih[:,E:E+HC]^T + b_ih  (loop-invariant)
    sgemm64<<<dim3(48, 8), 256>>>(ctx_h, HCC, nullptr,
                                  w_ih + EE, EE + HCC,
                                  pgictx, 3 * HLL, HCC,
                                  b_ih, nullptr, 0);

    float* hsbase = out + (size_t)TST * BB;   // all_lang_hs region

    for (int t = 0; t < TST; ++t) {
        // gi = emb[tok] @ w_ih[:,0:E]^T + gi_ctx
        sgemm64<<<dim3(48, 8), 256>>>(word_emb, EE, ptok,
                                      w_ih, EE + HCC,
                                      pgi, 3 * HLL, EE,
                                      nullptr, pgictx, 3 * HLL);
        // gh = h @ w_hh^T + b_hh
        sgemm64<<<dim3(48, 8), 256>>>(ph, HLL, nullptr,
                                      w_hh, HLL,
                                      pgh, 3 * HLL, HLL,
                                      b_hh, nullptr, 0);
        gru_act<<<2048, 256>>>(pgi, pgh, ph,
                               hsbase + (size_t)(t + 1) * BB * HLL);
        // dec = h @ dec_W^T + dec_b
        sgemm64<<<dim3(4, 8), 256>>>(ph, HLL, nullptr,
                                     dec_W, HLL,
                                     pdec, EE, HLL,
                                     dec_b, nullptr, 0);
        // logits = dec @ word_emb^T   (temperature == 1)
        sgemm128<<<dim3(250, 4), 256>>>(pdec, EE, word_emb, EE, plog, VV, EE);
        // sample (partitionable threefry gumbel-max)
        sample_kernel<<<512, 256>>>(plog, kk0[t], kk1[t],
                                    ptok, out + (size_t)t * BB);
    }

    // final extra GRU step (writes all_lang_hs slot 101)
    sgemm64<<<dim3(48, 8), 256>>>(word_emb, EE, ptok,
                                  w_ih, EE + HCC,
                                  pgi, 3 * HLL, EE,
                                  nullptr, pgictx, 3 * HLL);
    sgemm64<<<dim3(48, 8), 256>>>(ph, HLL, nullptr,
                                  w_hh, HLL,
                                  pgh, 3 * HLL, HLL,
                                  b_hh, nullptr, 0);
    gru_act<<<2048, 256>>>(pgi, pgh, ph,
                           hsbase + (size_t)(TST + 1) * BB * HLL);

    (void)in_sizes; (void)n_in; (void)out_size;
}

// round 9
// speedup vs baseline: 1.1432x; 1.1432x over previous
#include <cuda_runtime.h>

// Problem constants
#define VV   32000
#define EE   256
#define HLL  1024
#define HCC  256
#define BB   512
#define TST  100
#define DSPL 4        // dec split-K factor

// ---------------- scratch (__device__ globals, no allocation) ----------------
__device__ float g_h[BB * HLL];
__device__ float g_gi[BB * 3 * HLL];
__device__ float g_gh[BB * 3 * HLL];
__device__ float g_gictx[BB * 3 * HLL];
__device__ float g_dec[BB * EE];
__device__ float g_decpart[DSPL * BB * EE];
__device__ float g_logits[(size_t)BB * VV];
__device__ int   g_tok[BB];

// ---------------- threefry2x32 (Threefry-2x32, 20 rounds) ----------------
__host__ __device__ __forceinline__ unsigned int rotl32(unsigned int x, int r) {
    return (x << r) | (x >> (32 - r));
}

__host__ __device__ __forceinline__ void threefry2x32(
    unsigned int k0, unsigned int k1, unsigned int& x0, unsigned int& x1)
{
    unsigned int ks2 = k0 ^ k1 ^ 0x1BD11BDAu;
    x0 += k0; x1 += k1;
#define TF_R(r) { x0 += x1; x1 = rotl32(x1, (r)); x1 ^= x0; }
    TF_R(13) TF_R(15) TF_R(26) TF_R(6)   x0 += k1;  x1 += ks2 + 1u;
    TF_R(17) TF_R(29) TF_R(16) TF_R(24)  x0 += ks2; x1 += k0  + 2u;
    TF_R(13) TF_R(15) TF_R(26) TF_R(6)   x0 += k0;  x1 += k1  + 3u;
    TF_R(17) TF_R(29) TF_R(16) TF_R(24)  x0 += k1;  x1 += ks2 + 4u;
    TF_R(13) TF_R(15) TF_R(26) TF_R(6)   x0 += ks2; x1 += k0  + 5u;
#undef TF_R
}

// ---------------- flag-proof transcendentals (fmaf-only, faithful) ----------
__device__ __forceinline__ float acc_logf(float a) {
    int e = (__float_as_int(a) - 0x3f2aaaab) & 0xff800000;
    float m = __int_as_float(__float_as_int(a) - e);
    float i = (float)e * 1.19209290e-7f;   // e * 2^-23
    float f = m - 1.0f;
    float s = f * f;
    float r = fmaf(0.230836749f, f, -0.279208571f);
    float t = fmaf(0.331826031f, f, -0.498910338f);
    r = fmaf(r, s, t);
    r = fmaf(r, s, f);
    r = fmaf(i, 0.693147182f, r);
    return r;
}

__device__ __forceinline__ float acc_expf(float a) {
    float j = fmaf(1.442695041f, a, 12582912.0f) - 12582912.0f;  // rint(a/ln2)
    float f = fmaf(j, -6.93145752e-1f, a);   // ln2_hi
    f = fmaf(j, -1.42860677e-6f, f);         // ln2_lo
    float r = 1.37805939e-3f;
    r = fmaf(r, f, 8.37312452e-3f);
    r = fmaf(r, f, 4.16695364e-2f);
    r = fmaf(r, f, 1.66664720e-1f);
    r = fmaf(r, f, 4.99999851e-1f);
    r = fmaf(r, f, 1.0f);
    r = fmaf(r, f, 1.0f);
    int i = (int)j;
    return r * __int_as_float((127 + i) << 23);
}

__device__ __forceinline__ float acc_sigmoid(float x) {
    return 1.0f / (1.0f + acc_expf(-x));
}

__device__ __forceinline__ float acc_tanh(float x) {
    float t = acc_expf(2.0f * x);
    return (t - 1.0f) / (t + 1.0f);
}

__device__ __forceinline__ float gumbel_from_bits(unsigned int bits) {
    float f = __uint_as_float((bits >> 9) | 0x3f800000u) - 1.0f;
    const float TINY = 1.17549435e-38f;
    float u = fmaxf(TINY, f + TINY);
    return -acc_logf(-acc_logf(u));
}

// ---------------- init ----------------
__global__ void init_kernel(const float* __restrict__ lang_h0,
                            const int* __restrict__ inpt0,
                            float* __restrict__ out)
{
    int idx = blockIdx.x * blockDim.x + threadIdx.x;
    if (idx < BB * HLL) {
        float v = lang_h0[idx];
        g_h[idx] = v;
        out[(size_t)TST * BB + idx] = v;   // all_lang_hs slot 0
    }
    if (idx < BB) g_tok[idx] = inpt0[idx];
}

// ============================================================================
// 64x64x16 double-buffered SGEMM core (macro body shared by 3 kernels).
// A: [M,K] row-major (optional row gather), B: [N,K] row-major, C = A*B^T.
// ============================================================================
#define GEMM64_BODY(A, LDA, AROW, BM, LDB, C, LDC, K, BIAS, ADDM, LDADD, M0, N0) \
{                                                                              \
    __shared__ float As[2][16 * 68];                                           \
    __shared__ float Bs[2][16 * 68];                                           \
    int tid = threadIdx.x;                                                     \
    int tx = tid & 15, ty = tid >> 4;                                          \
    int lr = tid >> 2;                                                         \
    int lk = (tid & 3) * 4;                                                    \
    int am_ = (AROW) ? (AROW)[(M0) + lr] : ((M0) + lr);                        \
    const float* aptr = (A) + (size_t)am_ * (LDA) + lk;                        \
    const float* bptr = (BM) + (size_t)((N0) + lr) * (LDB) + lk;               \
    float4 ra = *(const float4*)aptr;                                          \
    float4 rb = *(const float4*)bptr;                                          \
    As[0][(lk + 0) * 68 + lr] = ra.x; As[0][(lk + 1) * 68 + lr] = ra.y;        \
    As[0][(lk + 2) * 68 + lr] = ra.z; As[0][(lk + 3) * 68 + lr] = ra.w;        \
    Bs[0][(lk + 0) * 68 + lr] = rb.x; Bs[0][(lk + 1) * 68 + lr] = rb.y;        \
    Bs[0][(lk + 2) * 68 + lr] = rb.z; Bs[0][(lk + 3) * 68 + lr] = rb.w;        \
    __syncthreads();                                                           \
    float acc[4][4] = {};                                                      \
    int nkt = (K) / 16;                                                        \
    for (int kt = 0; kt < nkt; ++kt) {                                         \
        int cur = kt & 1;                                                      \
        if (kt + 1 < nkt) {                                                    \
            ra = *(const float4*)(aptr + (kt + 1) * 16);                       \
            rb = *(const float4*)(bptr + (kt + 1) * 16);                       \
        }                                                                      \
        _Pragma("unroll")                                                      \
        for (int k = 0; k < 16; ++k) {                                         \
            float4 a = *(const float4*)&As[cur][k * 68 + ty * 4];              \
            float4 b = *(const float4*)&Bs[cur][k * 68 + tx * 4];              \
            float av[4] = {a.x, a.y, a.z, a.w};                                \
            float bv[4] = {b.x, b.y, b.z, b.w};                                \
            _Pragma("unroll")                                                  \
            for (int i = 0; i < 4; ++i)                                        \
                _Pragma("unroll")                                              \
                for (int j = 0; j < 4; ++j)                                    \
                    acc[i][j] = fmaf(av[i], bv[j], acc[i][j]);                 \
        }                                                                      \
        if (kt + 1 < nkt) {                                                    \
            int nxt = cur ^ 1;                                                 \
            As[nxt][(lk + 0) * 68 + lr] = ra.x; As[nxt][(lk + 1) * 68 + lr] = ra.y; \
            As[nxt][(lk + 2) * 68 + lr] = ra.z; As[nxt][(lk + 3) * 68 + lr] = ra.w; \
            Bs[nxt][(lk + 0) * 68 + lr] = rb.x; Bs[nxt][(lk + 1) * 68 + lr] = rb.y; \
            Bs[nxt][(lk + 2) * 68 + lr] = rb.z; Bs[nxt][(lk + 3) * 68 + lr] = rb.w; \
        }                                                                      \
        __syncthreads();                                                       \
    }                                                                          \
    _Pragma("unroll")                                                          \
    for (int i = 0; i < 4; ++i) {                                              \
        int m = (M0) + ty * 4 + i;                                             \
        int n = (N0) + tx * 4;                                                 \
        float4 v = make_float4(acc[i][0], acc[i][1], acc[i][2], acc[i][3]);    \
        if (BIAS) {                                                            \
            float4 bb = *(const float4*)&(BIAS)[n];                            \
            v.x += bb.x; v.y += bb.y; v.z += bb.z; v.w += bb.w;                \
        }                                                                      \
        if (ADDM) {                                                            \
            float4 ad = *(const float4*)&(ADDM)[(size_t)m * (LDADD) + n];      \
            v.x += ad.x; v.y += ad.y; v.z += ad.z; v.w += ad.w;                \
        }                                                                      \
        *(float4*)&(C)[(size_t)m * (LDC) + n] = v;                             \
    }                                                                          \
}

// ---------------- fused gates GEMM: z=0 -> gi, z=1 -> gh --------------------
__global__ void __launch_bounds__(256) gates_gemm(
    const float* __restrict__ word_emb, const int* __restrict__ tok,
    const float* __restrict__ w_ih, const float* __restrict__ gictx,
    float* __restrict__ gi,
    const float* __restrict__ h, const float* __restrict__ w_hh,
    const float* __restrict__ b_hh, float* __restrict__ gh)
{
    int m0 = blockIdx.y * 64, n0 = blockIdx.x * 64;
    if (blockIdx.z == 0) {
        // gi = emb[tok] @ w_ih[:, 0:E]^T + gictx
        GEMM64_BODY(word_emb, EE, tok, w_ih, (EE + HCC), gi, (3 * HLL), EE,
                    ((const float*)0), gictx, (3 * HLL), m0, n0);
    } else {
        // gh = h @ w_hh^T + b_hh
        GEMM64_BODY(h, HLL, ((const int*)0), w_hh, HLL, gh, (3 * HLL), HLL,
                    b_hh, ((const float*)0), 0, m0, n0);
    }
}

// ---------------- one-time gictx GEMM ---------------------------------------
__global__ void __launch_bounds__(256) gictx_gemm(
    const float* __restrict__ ctx_h, const float* __restrict__ w_ih,
    const float* __restrict__ b_ih, float* __restrict__ gictx)
{
    int m0 = blockIdx.y * 64, n0 = blockIdx.x * 64;
    GEMM64_BODY(ctx_h, HCC, ((const int*)0), (w_ih + EE), (EE + HCC),
                gictx, (3 * HLL), HCC, b_ih, ((const float*)0), 0, m0, n0);
}

// ---------------- dec split-K partial GEMM ----------------------------------
// z in [0,DSPL): partial[z] = h[:, z*256:(z+1)*256] @ dec_W[:, z*256:...]^T
__global__ void __launch_bounds__(256) dec_part_gemm(
    const float* __restrict__ h, const float* __restrict__ dec_W,
    float* __restrict__ part)
{
    int m0 = blockIdx.y * 64, n0 = blockIdx.x * 64;
    int koff = blockIdx.z * (HLL / DSPL);
    const float* A = h + koff;
    const float* B = dec_W + koff;
    float* C = part + (size_t)blockIdx.z * BB * EE;
    GEMM64_BODY(A, HLL, ((const int*)0), B, HLL, C, EE, (HLL / DSPL),
                ((const float*)0), ((const float*)0), 0, m0, n0);
}

__global__ void dec_reduce(const float* __restrict__ part,
                           const float* __restrict__ dec_b,
                           float* __restrict__ dec)
{
    int idx = blockIdx.x * blockDim.x + threadIdx.x;   // BB*EE
    float s = dec_b[idx & (EE - 1)];
#pragma unroll
    for (int z = 0; z < DSPL; ++z)
        s += part[(size_t)z * BB * EE + idx];
    dec[idx] = s;
}

// ---------------- SGEMM 128x128x16 double-buffered (logits) -----------------
__global__ void __launch_bounds__(256) sgemm128(
    const float* __restrict__ A, int lda,
    const float* __restrict__ Bm, int ldb,
    float* __restrict__ C, int ldc, int K)
{
    __shared__ float As[2][16 * 132];
    __shared__ float Bs[2][16 * 132];
    int tid = threadIdx.x;
    int tx = tid & 15, ty = tid >> 4;
    int m0 = blockIdx.y * 128, n0 = blockIdx.x * 128;
    int lr = tid >> 2;
    int lk = (tid & 3) * 4;

    const float* aptr0 = A + (size_t)(m0 + lr) * lda + lk;
    const float* aptr1 = A + (size_t)(m0 + lr + 64) * lda + lk;
    const float* bptr0 = Bm + (size_t)(n0 + lr) * ldb + lk;
    const float* bptr1 = Bm + (size_t)(n0 + lr + 64) * ldb + lk;

    float4 ra0 = *(const float4*)aptr0;
    float4 ra1 = *(const float4*)aptr1;
    float4 rb0 = *(const float4*)bptr0;
    float4 rb1 = *(const float4*)bptr1;

    As[0][(lk + 0) * 132 + lr] = ra0.x; As[0][(lk + 1) * 132 + lr] = ra0.y;
    As[0][(lk + 2) * 132 + lr] = ra0.z; As[0][(lk + 3) * 132 + lr] = ra0.w;
    As[0][(lk + 0) * 132 + lr + 64] = ra1.x; As[0][(lk + 1) * 132 + lr + 64] = ra1.y;
    As[0][(lk + 2) * 132 + lr + 64] = ra1.z; As[0][(lk + 3) * 132 + lr + 64] = ra1.w;
    Bs[0][(lk + 0) * 132 + lr] = rb0.x; Bs[0][(lk + 1) * 132 + lr] = rb0.y;
    Bs[0][(lk + 2) * 132 + lr] = rb0.z; Bs[0][(lk + 3) * 132 + lr] = rb0.w;
    Bs[0][(lk + 0) * 132 + lr + 64] = rb1.x; Bs[0][(lk + 1) * 132 + lr + 64] = rb1.y;
    Bs[0][(lk + 2) * 132 + lr + 64] = rb1.z; Bs[0][(lk + 3) * 132 + lr + 64] = rb1.w;
    __syncthreads();

    float acc[8][8] = {};
    int nkt = K / 16;
    for (int kt = 0; kt < nkt; ++kt) {
        int cur = kt & 1;
        if (kt + 1 < nkt) {
            ra0 = *(const float4*)(aptr0 + (kt + 1) * 16);
            ra1 = *(const float4*)(aptr1 + (kt + 1) * 16);
            rb0 = *(const float4*)(bptr0 + (kt + 1) * 16);
            rb1 = *(const float4*)(bptr1 + (kt + 1) * 16);
        }
#pragma unroll
        for (int k = 0; k < 16; ++k) {
            float4 a0 = *(const float4*)&As[cur][k * 132 + ty * 4];
            float4 a1 = *(const float4*)&As[cur][k * 132 + 64 + ty * 4];
            float4 b0 = *(const float4*)&Bs[cur][k * 132 + tx * 4];
            float4 b1 = *(const float4*)&Bs[cur][k * 132 + 64 + tx * 4];
            float av[8] = {a0.x, a0.y, a0.z, a0.w, a1.x, a1.y, a1.z, a1.w};
            float bv[8] = {b0.x, b0.y, b0.z, b0.w, b1.x, b1.y, b1.z, b1.w};
#pragma unroll
            for (int i = 0; i < 8; ++i)
#pragma unroll
                for (int j = 0; j < 8; ++j)
                    acc[i][j] = fmaf(av[i], bv[j], acc[i][j]);
        }
        if (kt + 1 < nkt) {
            int nxt = cur ^ 1;
            As[nxt][(lk + 0) * 132 + lr] = ra0.x; As[nxt][(lk + 1) * 132 + lr] = ra0.y;
            As[nxt][(lk + 2) * 132 + lr] = ra0.z; As[nxt][(lk + 3) * 132 + lr] = ra0.w;
            As[nxt][(lk + 0) * 132 + lr + 64] = ra1.x; As[nxt][(lk + 1) * 132 + lr + 64] = ra1.y;
            As[nxt][(lk + 2) * 132 + lr + 64] = ra1.z; As[nxt][(lk + 3) * 132 + lr + 64] = ra1.w;
            Bs[nxt][(lk + 0) * 132 + lr] = rb0.x; Bs[nxt][(lk + 1) * 132 + lr] = rb0.y;
            Bs[nxt][(lk + 2) * 132 + lr] = rb0.z; Bs[nxt][(lk + 3) * 132 + lr] = rb0.w;
            Bs[nxt][(lk + 0) * 132 + lr + 64] = rb1.x; Bs[nxt][(lk + 1) * 132 + lr + 64] = rb1.y;
            Bs[nxt][(lk + 2) * 132 + lr + 64] = rb1.z; Bs[nxt][(lk + 3) * 132 + lr + 64] = rb1.w;
        }
        __syncthreads();
    }

#pragma unroll
    for (int i = 0; i < 8; ++i) {
        int m = m0 + (i < 4 ? ty * 4 + i : 64 + ty * 4 + (i - 4));
        float* crow = C + (size_t)m * ldc;
        *(float4*)&crow[n0 + tx * 4] =
            make_float4(acc[i][0], acc[i][1], acc[i][2], acc[i][3]);
        *(float4*)&crow[n0 + 64 + tx * 4] =
            make_float4(acc[i][4], acc[i][5], acc[i][6], acc[i][7]);
    }
}

// ---------------- GRU elementwise ----------------
__global__ void gru_act(const float* __restrict__ gi, const float* __restrict__ gh,
                        float* __restrict__ h, float* __restrict__ hs_out)
{
    int idx = blockIdx.x * blockDim.x + threadIdx.x;   // BB*HLL
    int b = idx >> 10, j = idx & 1023;
    size_t base = (size_t)b * 3072 + j;
    float ir = gi[base], iz = gi[base + 1024], in_ = gi[base + 2048];
    float hr = gh[base], hz = gh[base + 1024], hn = gh[base + 2048];
    float r = acc_sigmoid(ir + hr);
    float z = acc_sigmoid(iz + hz);
    float n = acc_tanh(in_ + r * hn);
    float hprev = h[idx];
    float hnew = (1.0f - z) * n + z * hprev;
    h[idx] = hnew;
    hs_out[idx] = hnew;
}

// ---------------- sampler: partitionable threefry + gumbel + argmax ---------
__global__ void __launch_bounds__(256) sample_kernel(
    const float* __restrict__ logits,
    unsigned int k0, unsigned int k1,
    int* __restrict__ tok, float* __restrict__ outtok)
{
    int b = blockIdx.x;            // 0..511
    int tid = threadIdx.x;
    const float* l = logits + (size_t)b * VV;

    float best = -1e30f;
    int bi = 0;
    unsigned int jbase = (unsigned int)b * (unsigned int)VV;

    for (int v = tid; v < VV; v += 256) {
        unsigned int x0 = 0u;
        unsigned int x1 = jbase + (unsigned int)v;
        threefry2x32(k0, k1, x0, x1);
        unsigned int bits = x0 ^ x1;
        float c = l[v] + gumbel_from_bits(bits);
        if (c > best) { best = c; bi = v; }
    }

    __shared__ float sv[256];
    __shared__ int   si[256];
    sv[tid] = best; si[tid] = bi;
    __syncthreads();
    for (int s = 128; s > 0; s >>= 1) {
        if (tid < s) {
            float v2 = sv[tid + s]; int i2 = si[tid + s];
            float v1 = sv[tid];     int i1 = si[tid];
            if (v2 > v1 || (v2 == v1 && i2 < i1)) { sv[tid] = v2; si[tid] = i2; }
        }
        __syncthreads();
    }
    if (tid == 0) {
        tok[b] = si[0];
        outtok[b] = (float)si[0];
    }
}

// ---------------- host driver ----------------
extern "C" void kernel_launch(void* const* d_in, const int* in_sizes, int n_in,
                              void* d_out, int out_size)
{
    const float* lang_h0  = (const float*)d_in[0];
    const float* ctx_h    = (const float*)d_in[1];
    const float* word_emb = (const float*)d_in[2];
    const float* dec_W    = (const float*)d_in[3];
    const float* dec_b    = (const float*)d_in[4];
    const float* w_ih     = (const float*)d_in[5];
    const float* w_hh     = (const float*)d_in[6];
    const float* b_ih     = (const float*)d_in[7];
    const float* b_hh     = (const float*)d_in[8];
    const int*   inpt0    = (const int*)d_in[9];
    float* out = (float*)d_out;

    float *ph, *pgi, *pgh, *pgictx, *pdec, *pdecp, *plog;
    int* ptok;
    cudaGetSymbolAddress((void**)&ph, g_h);
    cudaGetSymbolAddress((void**)&pgi, g_gi);
    cudaGetSymbolAddress((void**)&pgh, g_gh);
    cudaGetSymbolAddress((void**)&pgictx, g_gictx);
    cudaGetSymbolAddress((void**)&pdec, g_dec);
    cudaGetSymbolAddress((void**)&pdecp, g_decpart);
    cudaGetSymbolAddress((void**)&plog, g_logits);
    cudaGetSymbolAddress((void**)&ptok, g_tok);

    // Host-side key schedule, PARTITIONABLE mode:
    // key_t = threefry2x32(key=(0,1), x0=0, x1=t)
    unsigned int kk0[TST], kk1[TST];
    for (int t = 0; t < TST; ++t) {
        unsigned int x0 = 0u, x1 = (unsigned int)t;
        threefry2x32(0u, 1u, x0, x1);
        kk0[t] = x0;
        kk1[t] = x1;
    }

    init_kernel<<<2048, 256>>>(lang_h0, inpt0, out);

    // gi_ctx = ctx_h @ w_ih[:,E:E+HC]^T + b_ih  (loop-invariant)
    gictx_gemm<<<dim3(48, 8), 256>>>(ctx_h, w_ih, b_ih, pgictx);

    float* hsbase = out + (size_t)TST * BB;   // all_lang_hs region

    for (int t = 0; t < TST; ++t) {
        // gi + gh fused (z=0: gi gather-GEMM, z=1: gh GEMM)
        gates_gemm<<<dim3(48, 8, 2), 256>>>(word_emb, ptok, w_ih, pgictx, pgi,
                                            ph, w_hh, b_hh, pgh);
        gru_act<<<2048, 256>>>(pgi, pgh, ph,
                               hsbase + (size_t)(t + 1) * BB * HLL);
        // dec = h @ dec_W^T + dec_b  (split-K x4, deterministic reduce)
        dec_part_gemm<<<dim3(4, 8, DSPL), 256>>>(ph, dec_W, pdecp);
        dec_reduce<<<512, 256>>>(pdecp, dec_b, pdec);
        // logits = dec @ word_emb^T   (temperature == 1)
        sgemm128<<<dim3(250, 4), 256>>>(pdec, EE, word_emb, EE, plog, VV, EE);
        // sample (partitionable threefry gumbel-max)
        sample_kernel<<<512, 256>>>(plog, kk0[t], kk1[t],
                                    ptok, out + (size_t)t * BB);
    }

    // final extra GRU step (writes all_lang_hs slot 101)
    gates_gemm<<<dim3(48, 8, 2), 256>>>(word_emb, ptok, w_ih, pgictx, pgi,
                                        ph, w_hh, b_hh, pgh);
    gru_act<<<2048, 256>>>(pgi, pgh, ph,
                           hsbase + (size_t)(TST + 1) * BB * HLL);

    (void)in_sizes; (void)n_in; (void)out_size;
}